// round 16
// baseline (speedup 1.0000x reference)
#include <cuda_runtime.h>
#include <cuda_fp16.h>
#include <math.h>
#include <stdint.h>

#define DIM 1024
#define NH 16
#define HD 64
#define BATCH 4
#define SEQ 1024
#define BS (BATCH*SEQ)
#define MLP_HID 4096
#define LN_EPS 1e-5f

// ---------------- scratch ----------------
__device__ float  g_mod[BATCH * 6 * DIM];
__device__ __half g_h[BS * DIM];
__device__ __half g_qkv[BS * 3 * DIM];
__device__ __half g_o[BS * DIM];
__device__ float  g_x2[BS * DIM];
__device__ __half g_mid[BS * MLP_HID];
#define WO_QKV  0
#define WO_ATTN (3*DIM*DIM)
#define WO_MLP1 (WO_ATTN + DIM*DIM)
#define WO_MLP2 (WO_MLP1 + DIM*MLP_HID)
#define W_TOTAL (WO_MLP2 + MLP_HID*DIM)
__device__ __half g_wh[W_TOTAL];

// ================= helpers =================
__device__ __forceinline__ void mma16(float* c, const uint32_t* a, const uint32_t* b) {
    asm volatile(
        "mma.sync.aligned.m16n8k16.row.col.f32.f16.f16.f32 "
        "{%0,%1,%2,%3}, {%4,%5,%6,%7}, {%8,%9}, {%0,%1,%2,%3};"
        : "+f"(c[0]), "+f"(c[1]), "+f"(c[2]), "+f"(c[3])
        : "r"(a[0]), "r"(a[1]), "r"(a[2]), "r"(a[3]), "r"(b[0]), "r"(b[1]));
}
__device__ __forceinline__ void ldsm4(uint32_t* r, uint32_t addr) {
    asm volatile("ldmatrix.sync.aligned.m8n8.x4.shared.b16 {%0,%1,%2,%3}, [%4];"
        : "=r"(r[0]), "=r"(r[1]), "=r"(r[2]), "=r"(r[3]) : "r"(addr));
}
__device__ __forceinline__ void ldsm4t(uint32_t* r, uint32_t addr) {
    asm volatile("ldmatrix.sync.aligned.m8n8.x4.trans.shared.b16 {%0,%1,%2,%3}, [%4];"
        : "=r"(r[0]), "=r"(r[1]), "=r"(r[2]), "=r"(r[3]) : "r"(addr));
}
__device__ __forceinline__ void ldsm2t(uint32_t* r, uint32_t addr) {
    asm volatile("ldmatrix.sync.aligned.m8n8.x2.trans.shared.b16 {%0,%1}, [%2];"
        : "=r"(r[0]), "=r"(r[1]) : "r"(addr));
}
__device__ __forceinline__ uint32_t packh2(float a, float b) {
    __half2 h = __floats2half2_rn(a, b);
    return *(uint32_t*)&h;
}
__device__ __forceinline__ float gelu_f(float u) {
    float y = 0.7978845608028654f * (u + 0.044715f * u * u * u);
    float e = __expf(2.0f * y);
    return u * (1.0f - __fdividef(1.0f, e + 1.0f));
}

#define CP16(smem, gmem) \
    asm volatile("cp.async.cg.shared.global [%0], [%1], 16;" :: "r"(smem), "l"(gmem))
#define CP_COMMIT() asm volatile("cp.async.commit_group;" ::: "memory")
#define CP_WAIT1()  asm volatile("cp.async.wait_group 1;" ::: "memory")

// ---------------- prep1: qkv weight cvt + adaLN modulation ----------------
#define QKV_CVT_BLOCKS ((WO_ATTN/8 + 255)/256)
#define ADA_BLOCKS ((6*DIM + 255)/256)
__global__ void prep1_kernel(const float* __restrict__ wqkv,
                             const float* __restrict__ c,
                             const float* __restrict__ w_ada,
                             const float* __restrict__ b_ada)
{
    if (blockIdx.x < QKV_CVT_BLOCKS) {
        int i = (blockIdx.x * blockDim.x + threadIdx.x) * 8;
        if (i >= WO_ATTN) return;
        float4 v0 = *(const float4*)(wqkv + i);
        float4 v1 = *(const float4*)(wqkv + i + 4);
        uint4 u;
        u.x = packh2(v0.x, v0.y); u.y = packh2(v0.z, v0.w);
        u.z = packh2(v1.x, v1.y); u.w = packh2(v1.z, v1.w);
        *(uint4*)(g_wh + i) = u;
    } else {
        int j = (blockIdx.x - QKV_CVT_BLOCKS) * blockDim.x + threadIdx.x;
        if (j >= 6 * DIM) return;
        float s0 = b_ada[j], s1 = s0, s2 = s0, s3 = s0;
        for (int k = 0; k < DIM; k++) {
            float w = w_ada[k * (6 * DIM) + j];
            s0 += c[k] * w;
            s1 += c[DIM + k] * w;
            s2 += c[2 * DIM + k] * w;
            s3 += c[3 * DIM + k] * w;
        }
        g_mod[j] = s0;
        g_mod[6 * DIM + j] = s1;
        g_mod[12 * DIM + j] = s2;
        g_mod[18 * DIM + j] = s3;
    }
}

// ============ fp16 mma GEMM, BK=64, 2-stage cp.async, 2 CTA/SM ============
#define PADA 72
#define PADB 136
#define ASZH (128 * PADA)
#define BSZH (64 * PADB)
#define STGB ((ASZH + BSZH) * 2)
#define NSTAGE 2
#define GSMEM (NSTAGE * STGB)
#define EBROW 136

__global__ void __launch_bounds__(256, 2)
tgemm_kernel(const __half* __restrict__ A,
             const __half* __restrict__ B,
             const float* __restrict__ bias,
             const float* __restrict__ resid,
             void* __restrict__ C,
             int M, int N, int K, int act, int gate_chunk, int out_half,
             int rope, const float* __restrict__ cosb, const float* __restrict__ sinb)
{
    extern __shared__ char fsraw[];
    const uint32_t smb = (uint32_t)__cvta_generic_to_shared(fsraw);

    const int t = threadIdx.x, lane = t & 31, wid = t >> 5;
    const int warpM = wid >> 2, warpN = wid & 3;
    const int bm = blockIdx.y * 128, bn = blockIdx.x * 128;
    const int gid = lane >> 2, tig = lane & 3;

    const int am = (t * 8) >> 6;
    const int ak = (t * 8) & 63;
    const int bk = (t * 8) >> 7;
    const int bnn = (t * 8) & 127;

    float acc[4][4][4];
    #pragma unroll
    for (int i = 0; i < 4; i++)
        #pragma unroll
        for (int j = 0; j < 4; j++)
            #pragma unroll
            for (int q = 0; q < 4; q++) acc[i][j][q] = 0.f;

    const int NC = K >> 6;

    auto issue = [&](int stage, int kc) {
        uint32_t abase = smb + (uint32_t)(stage * STGB);
        uint32_t bbase = abase + (uint32_t)(ASZH * 2);
        #pragma unroll
        for (int i = 0; i < 4; i++) {
            int m = am + i * 32;
            CP16(abase + (uint32_t)(m * PADA + ak) * 2u,
                 A + (size_t)(bm + m) * K + kc * 64 + ak);
        }
        #pragma unroll
        for (int i = 0; i < 4; i++) {
            int kk = bk + i * 16;
            CP16(bbase + (uint32_t)(kk * PADB + bnn) * 2u,
                 B + (size_t)(kc * 64 + kk) * N + bn + bnn);
        }
    };

    issue(0, 0); CP_COMMIT();
    if (NC > 1) issue(1, 1);
    CP_COMMIT();

    const int arow = warpM * 64 + (lane & 15);
    const int akof = (lane >> 4) * 8;
    const int bkl = lane & 15;
    const int bgof = (lane >> 4) * 8;

    for (int kc = 0; kc < NC; kc++) {
        CP_WAIT1();
        __syncthreads();

        const uint32_t sA = smb + (uint32_t)((kc & 1) * STGB);
        const uint32_t sB = sA + (uint32_t)(ASZH * 2);

        #pragma unroll
        for (int ks = 0; ks < 4; ks++) {
            uint32_t af[4][4], bf[2][4];
            #pragma unroll
            for (int mi = 0; mi < 4; mi++) {
                int row = arow + mi * 16;
                ldsm4(af[mi], sA + (uint32_t)(row * PADA + ks * 16 + akof) * 2u);
            }
            #pragma unroll
            for (int g = 0; g < 2; g++) {
                int n0 = warpN * 32 + g * 16 + bgof;
                int k = ks * 16 + bkl;
                ldsm4t(bf[g], sB + (uint32_t)(k * PADB + n0) * 2u);
            }
            #pragma unroll
            for (int mi = 0; mi < 4; mi++)
                #pragma unroll
                for (int ni = 0; ni < 4; ni++)
                    mma16(acc[mi][ni], af[mi], &bf[ni >> 1][(ni & 1) * 2]);
        }

        if (kc + 2 < NC) {
            __syncthreads();
            issue(kc & 1, kc + 2);
        }
        CP_COMMIT();
    }

    // ---- epilogue ----
    if (rope && bn < 2 * DIM) {
        __half* eb = (__half*)fsraw;
        __syncthreads();
        #pragma unroll
        for (int mi = 0; mi < 4; mi++) {
            #pragma unroll
            for (int ni = 0; ni < 4; ni++) {
                int rl = warpM * 64 + mi * 16 + gid;
                int cl = warpN * 32 + ni * 8 + tig * 2;
                *(uint32_t*)&eb[rl * EBROW + cl] =
                    packh2(acc[mi][ni][0], acc[mi][ni][1]);
                *(uint32_t*)&eb[(rl + 8) * EBROW + cl] =
                    packh2(acc[mi][ni][2], acc[mi][ni][3]);
            }
        }
        __syncthreads();
        __half* Ch = (__half*)C;
        #pragma unroll
        for (int j = 0; j < 32; j++) {
            int p2 = j * 256 + t;
            int r = p2 >> 6;
            int q = p2 & 63;
            int hoff = (q >> 5) * 64;
            int i = q & 31;
            int grow = bm + r;
            int s = grow & (SEQ - 1);
            float co = cosb[s * 32 + i];
            float si = sinb[s * 32 + i];
            float v1 = __half2float(eb[r * EBROW + hoff + i]);
            float v2 = __half2float(eb[r * EBROW + hoff + i + 32]);
            size_t base = (size_t)grow * N + bn + hoff;
            Ch[base + i]      = __float2half_rn(v1 * co - v2 * si);
            Ch[base + i + 32] = __float2half_rn(v2 * co + v1 * si);
        }
        return;
    }

    #pragma unroll
    for (int mi = 0; mi < 4; mi++) {
        #pragma unroll
        for (int ni = 0; ni < 4; ni++) {
            int r0 = bm + warpM * 64 + mi * 16 + gid;
            int c0 = bn + warpN * 32 + ni * 8 + tig * 2;
            float v0 = acc[mi][ni][0], v1 = acc[mi][ni][1];
            float v2 = acc[mi][ni][2], v3 = acc[mi][ni][3];
            if (bias) {
                float b0 = bias[c0], b1 = bias[c0 + 1];
                v0 += b0; v1 += b1; v2 += b0; v3 += b1;
            }
            if (act) {
                v0 = gelu_f(v0); v1 = gelu_f(v1);
                v2 = gelu_f(v2); v3 = gelu_f(v3);
            }
            if (resid) {
                const float* gp0 = g_mod + (r0 >> 10) * 6 * DIM + gate_chunk * DIM + c0;
                const float* gp1 = g_mod + ((r0 + 8) >> 10) * 6 * DIM + gate_chunk * DIM + c0;
                float2 rr0 = *(const float2*)(resid + (size_t)r0 * N + c0);
                float2 rr1 = *(const float2*)(resid + (size_t)(r0 + 8) * N + c0);
                v0 = rr0.x + gp0[0] * v0;
                v1 = rr0.y + gp0[1] * v1;
                v2 = rr1.x + gp1[0] * v2;
                v3 = rr1.y + gp1[1] * v3;
            }
            if (out_half) {
                __half* Ch = (__half*)C;
                *(uint32_t*)(Ch + (size_t)r0 * N + c0)       = packh2(v0, v1);
                *(uint32_t*)(Ch + (size_t)(r0 + 8) * N + c0) = packh2(v2, v3);
            } else {
                float* Cf = (float*)C;
                *(float2*)(Cf + (size_t)r0 * N + c0)       = make_float2(v0, v1);
                *(float2*)(Cf + (size_t)(r0 + 8) * N + c0) = make_float2(v2, v3);
            }
        }
    }
}

// ============ fused flash attention + hidden weight conversion ============
// Blocks [0, 1024): attention (R9-exact). Blocks [1024, ...): convert
// attn/mlp weights fp32->fp16 (consumed only after this launch).
#define FP 72
#define KVT (64 * FP)
#define FLASH_BLOCKS 1024
#define REST_ELEMS (W_TOTAL - WO_ATTN)
#define CVT2_PER (128 * 8 * 4)
#define CVT2_BLOCKS ((REST_ELEMS + CVT2_PER - 1) / CVT2_PER)

__global__ void __launch_bounds__(128)
flash_kernel(const float* __restrict__ wattn,
             const float* __restrict__ wmlp1,
             const float* __restrict__ wmlp2)
{
    __shared__ __align__(16) __half Qs[KVT];
    __shared__ __align__(16) __half Ks[3][KVT];
    __shared__ __align__(16) __half Vs[3][KVT];

    const int bid = blockIdx.x;
    const int t = threadIdx.x;

    if (bid >= FLASH_BLOCKS) {
        // weight conversion branch
        int base = (bid - FLASH_BLOCKS) * CVT2_PER + t * 8;
        #pragma unroll
        for (int it2 = 0; it2 < 4; it2++) {
            int i = base + it2 * 1024;
            if (i >= REST_ELEMS) return;
            const float* src;
            int off;
            if (i < WO_MLP1 - WO_ATTN)      { src = wattn; off = i; }
            else if (i < WO_MLP2 - WO_ATTN) { src = wmlp1; off = i - (WO_MLP1 - WO_ATTN); }
            else                            { src = wmlp2; off = i - (WO_MLP2 - WO_ATTN); }
            float4 v0 = *(const float4*)(src + off);
            float4 v1 = *(const float4*)(src + off + 4);
            uint4 u;
            u.x = packh2(v0.x, v0.y); u.y = packh2(v0.z, v0.w);
            u.z = packh2(v1.x, v1.y); u.w = packh2(v1.z, v1.w);
            *(uint4*)(g_wh + WO_ATTN + i) = u;
        }
        return;
    }

    const int lane = t & 31, wid = t >> 5;
    const int gid = lane >> 2, tig = lane & 3;
    const int bh = bid >> 4, b = bh >> 4, h = bh & 15;
    const int q0 = (bid & 15) * 64;
    const int row = wid * 16 + gid;

    const int fr = (t * 8) >> 6;
    const int fc = (t * 8) & 63;

    auto issue_kv = [&](int buf, int kt) {
        uint32_t kb = (uint32_t)__cvta_generic_to_shared(&Ks[buf][0]);
        uint32_t vbuf = (uint32_t)__cvta_generic_to_shared(&Vs[buf][0]);
        #pragma unroll
        for (int i = 0; i < 4; i++) {
            int r = fr + i * 16;
            const __half* kg = g_qkv + ((size_t)(b * SEQ + kt + r) * 3 + 1) * 1024 + h * 64 + fc;
            const __half* vg = g_qkv + ((size_t)(b * SEQ + kt + r) * 3 + 2) * 1024 + h * 64 + fc;
            CP16(kb   + (uint32_t)(r * FP + fc) * 2u, kg);
            CP16(vbuf + (uint32_t)(r * FP + fc) * 2u, vg);
        }
    };

    #pragma unroll
    for (int i = 0; i < 4; i++) {
        int e = (i * 128 + t) * 8;
        int r = e >> 6, c = e & 63;
        *(uint4*)&Qs[r * FP + c] =
            *(const uint4*)(g_qkv + ((size_t)(b * SEQ + q0 + r) * 3) * 1024 + h * 64 + c);
    }

    issue_kv(0, 0); CP_COMMIT();
    issue_kv(1, 64); CP_COMMIT();

    float m_i[2] = { -1e30f, -1e30f };
    float l_i[2] = { 0.f, 0.f };
    float oacc[8][4];
    #pragma unroll
    for (int ni = 0; ni < 8; ni++)
        #pragma unroll
        for (int q = 0; q < 4; q++) oacc[ni][q] = 0.f;

    for (int it = 0; it < SEQ / 64; it++) {
        CP_WAIT1();
        __syncthreads();

        if (it + 2 < SEQ / 64) issue_kv((it + 2) % 3, (it + 2) * 64);
        CP_COMMIT();

        const __half* Kc = Ks[it % 3];
        const uint32_t vb = (uint32_t)__cvta_generic_to_shared(&Vs[it % 3][0]);

        float sacc[8][4];
        #pragma unroll
        for (int ni = 0; ni < 8; ni++)
            #pragma unroll
            for (int q = 0; q < 4; q++) sacc[ni][q] = 0.f;

        #pragma unroll
        for (int ks = 0; ks < 4; ks++) {
            uint32_t af[4];
            af[0] = *(uint32_t*)&Qs[row * FP + ks * 16 + 2 * tig];
            af[1] = *(uint32_t*)&Qs[(row + 8) * FP + ks * 16 + 2 * tig];
            af[2] = *(uint32_t*)&Qs[row * FP + ks * 16 + 8 + 2 * tig];
            af[3] = *(uint32_t*)&Qs[(row + 8) * FP + ks * 16 + 8 + 2 * tig];
            #pragma unroll
            for (int ni = 0; ni < 8; ni++) {
                int n = ni * 8 + gid;
                uint32_t bf[2];
                bf[0] = *(const uint32_t*)&Kc[n * FP + ks * 16 + 2 * tig];
                bf[1] = *(const uint32_t*)&Kc[n * FP + ks * 16 + 8 + 2 * tig];
                mma16(sacc[ni], af, bf);
            }
        }

        #pragma unroll
        for (int ni = 0; ni < 8; ni++)
            #pragma unroll
            for (int q = 0; q < 4; q++) sacc[ni][q] *= 0.125f;

        float rmax[2] = { -1e30f, -1e30f };
        #pragma unroll
        for (int ni = 0; ni < 8; ni++) {
            rmax[0] = fmaxf(rmax[0], fmaxf(sacc[ni][0], sacc[ni][1]));
            rmax[1] = fmaxf(rmax[1], fmaxf(sacc[ni][2], sacc[ni][3]));
        }
        #pragma unroll
        for (int w = 1; w <= 2; w <<= 1) {
            rmax[0] = fmaxf(rmax[0], __shfl_xor_sync(0xffffffff, rmax[0], w));
            rmax[1] = fmaxf(rmax[1], __shfl_xor_sync(0xffffffff, rmax[1], w));
        }
        float mnew0 = fmaxf(m_i[0], rmax[0]);
        float mnew1 = fmaxf(m_i[1], rmax[1]);
        float alpha0 = __expf(m_i[0] - mnew0);
        float alpha1 = __expf(m_i[1] - mnew1);
        m_i[0] = mnew0; m_i[1] = mnew1;

        float rsum[2] = { 0.f, 0.f };
        #pragma unroll
        for (int ni = 0; ni < 8; ni++) {
            sacc[ni][0] = __expf(sacc[ni][0] - mnew0);
            sacc[ni][1] = __expf(sacc[ni][1] - mnew0);
            sacc[ni][2] = __expf(sacc[ni][2] - mnew1);
            sacc[ni][3] = __expf(sacc[ni][3] - mnew1);
            rsum[0] += sacc[ni][0] + sacc[ni][1];
            rsum[1] += sacc[ni][2] + sacc[ni][3];
        }
        #pragma unroll
        for (int w = 1; w <= 2; w <<= 1) {
            rsum[0] += __shfl_xor_sync(0xffffffff, rsum[0], w);
            rsum[1] += __shfl_xor_sync(0xffffffff, rsum[1], w);
        }
        l_i[0] = l_i[0] * alpha0 + rsum[0];
        l_i[1] = l_i[1] * alpha1 + rsum[1];

        #pragma unroll
        for (int ni = 0; ni < 8; ni++) {
            oacc[ni][0] *= alpha0; oacc[ni][1] *= alpha0;
            oacc[ni][2] *= alpha1; oacc[ni][3] *= alpha1;
        }

        #pragma unroll
        for (int ks = 0; ks < 4; ks++) {
            uint32_t af[4];
            af[0] = packh2(sacc[2*ks][0],   sacc[2*ks][1]);
            af[1] = packh2(sacc[2*ks][2],   sacc[2*ks][3]);
            af[2] = packh2(sacc[2*ks+1][0], sacc[2*ks+1][1]);
            af[3] = packh2(sacc[2*ks+1][2], sacc[2*ks+1][3]);
            int k = ks * 16 + (lane & 15);
            #pragma unroll
            for (int ni = 0; ni < 8; ni++) {
                uint32_t bf[2];
                ldsm2t(bf, vb + (uint32_t)(k * FP + ni * 8) * 2u);
                mma16(oacc[ni], af, bf);
            }
        }
    }

    float inv0 = __fdividef(1.0f, l_i[0]);
    float inv1 = __fdividef(1.0f, l_i[1]);
    #pragma unroll
    for (int ni = 0; ni < 8; ni++) {
        int c = h * 64 + ni * 8 + tig * 2;
        __half* op0 = g_o + (size_t)(b * SEQ + q0 + row) * 1024 + c;
        __half* op1 = g_o + (size_t)(b * SEQ + q0 + row + 8) * 1024 + c;
        *(uint32_t*)op0 = packh2(oacc[ni][0] * inv0, oacc[ni][1] * inv0);
        *(uint32_t*)op1 = packh2(oacc[ni][2] * inv1, oacc[ni][3] * inv1);
    }
}

// ---------------- LayerNorm + modulate -> half (shuffle reduction) ----------------
__global__ void ln_mod_kernel(const float* __restrict__ x,
                              const float* __restrict__ w,
                              int shift_chunk, int scale_chunk,
                              __half* __restrict__ out)
{
    int row = blockIdx.x;
    int b = row >> 10;
    int t = threadIdx.x;
    int lane = t & 31, wid = t >> 5;
    const float* xr = x + (size_t)row * DIM;
    float4 v = *(const float4*)(xr + t * 4);
    float sum = v.x + v.y + v.z + v.w;
    float sq  = v.x*v.x + v.y*v.y + v.z*v.z + v.w*v.w;

    #pragma unroll
    for (int o = 16; o > 0; o >>= 1) {
        sum += __shfl_xor_sync(0xffffffff, sum, o);
        sq  += __shfl_xor_sync(0xffffffff, sq,  o);
    }
    __shared__ float ws[8], ws2[8];
    if (lane == 0) { ws[wid] = sum; ws2[wid] = sq; }
    __syncthreads();
    if (wid == 0) {
        float a = (lane < 8) ? ws[lane] : 0.f;
        float c2 = (lane < 8) ? ws2[lane] : 0.f;
        #pragma unroll
        for (int o = 4; o > 0; o >>= 1) {
            a  += __shfl_xor_sync(0xffffffff, a, o);
            c2 += __shfl_xor_sync(0xffffffff, c2, o);
        }
        if (lane == 0) { ws[0] = a; ws2[0] = c2; }
    }
    __syncthreads();
    float mean = ws[0] * (1.0f / DIM);
    float var  = ws2[0] * (1.0f / DIM) - mean * mean;
    float rstd = rsqrtf(var + LN_EPS);

    const float* shiftp = g_mod + b * 6 * DIM + shift_chunk * DIM;
    const float* scalep = g_mod + b * 6 * DIM + scale_chunk * DIM;
    __half* orow = out + (size_t)row * DIM;
    float y[4];
    #pragma unroll
    for (int u = 0; u < 4; u++) {
        int col = t * 4 + u;
        float xv = (u == 0) ? v.x : (u == 1) ? v.y : (u == 2) ? v.z : v.w;
        float yy = (xv - mean) * rstd * w[col];
        y[u] = yy * (1.0f + scalep[col]) + shiftp[col];
    }
    uint2 pk;
    pk.x = packh2(y[0], y[1]);
    pk.y = packh2(y[2], y[3]);
    *(uint2*)(orow + t * 4) = pk;
}

// ---------------- launch ----------------
extern "C" void kernel_launch(void* const* d_in, const int* in_sizes, int n_in,
                              void* d_out, int out_size)
{
    const float* x          = (const float*)d_in[0];
    const float* cosb       = (const float*)d_in[1];
    const float* sinb       = (const float*)d_in[2];
    const float* c          = (const float*)d_in[3];
    const float* w_ln1      = (const float*)d_in[4];
    const float* w_ln2      = (const float*)d_in[5];
    const float* w_qkv      = (const float*)d_in[6];
    const float* w_attn_out = (const float*)d_in[7];
    const float* w_mlp1     = (const float*)d_in[8];
    const float* b_mlp1     = (const float*)d_in[9];
    const float* w_mlp2     = (const float*)d_in[10];
    const float* b_mlp2     = (const float*)d_in[11];
    const float* w_ada      = (const float*)d_in[12];
    const float* b_ada      = (const float*)d_in[13];
    float* out = (float*)d_out;

    __half *p_h, *p_qkv, *p_o, *p_mid, *p_wh;
    float *p_x2;
    cudaGetSymbolAddress((void**)&p_h,   g_h);
    cudaGetSymbolAddress((void**)&p_qkv, g_qkv);
    cudaGetSymbolAddress((void**)&p_o,   g_o);
    cudaGetSymbolAddress((void**)&p_x2,  g_x2);
    cudaGetSymbolAddress((void**)&p_mid, g_mid);
    cudaGetSymbolAddress((void**)&p_wh,  g_wh);

    cudaFuncSetAttribute(tgemm_kernel,
                         cudaFuncAttributeMaxDynamicSharedMemorySize, GSMEM);

    // 1. qkv weight cvt + adaLN modulation
    prep1_kernel<<<QKV_CVT_BLOCKS + ADA_BLOCKS, 256>>>(w_qkv, c, w_ada, b_ada);

    // 2. LN1 + modulate
    ln_mod_kernel<<<BS, 256>>>(x, w_ln1, 0, 1, p_h);

    // 3. qkv = h @ w_qkv  (RoPE fused into epilogue for q/k planes)
    tgemm_kernel<<<dim3(3 * DIM / 128, BS / 128), 256, GSMEM>>>(
        p_h, p_wh + WO_QKV, nullptr, nullptr, p_qkv, BS, 3 * DIM, DIM, 0, 0, 1,
        1, cosb, sinb);

    // 4. fused attention + hidden attn/mlp weight conversion
    flash_kernel<<<FLASH_BLOCKS + CVT2_BLOCKS, 128>>>(w_attn_out, w_mlp1, w_mlp2);

    // 5. x2 = x + gate_msa * (o @ w_attn_out)
    tgemm_kernel<<<dim3(DIM / 128, BS / 128), 256, GSMEM>>>(
        p_o, p_wh + WO_ATTN, nullptr, x, p_x2, BS, DIM, DIM, 0, 2, 0,
        0, nullptr, nullptr);

    // 6. LN2 + modulate
    ln_mod_kernel<<<BS, 256>>>(p_x2, w_ln2, 3, 4, p_h);

    // 7. mid = gelu(h @ w_mlp1 + b_mlp1)
    tgemm_kernel<<<dim3(MLP_HID / 128, BS / 128), 256, GSMEM>>>(
        p_h, p_wh + WO_MLP1, b_mlp1, nullptr, p_mid, BS, MLP_HID, DIM, 1, 0, 1,
        0, nullptr, nullptr);

    // 8. out = x2 + gate_mlp * (mid @ w_mlp2 + b_mlp2)
    tgemm_kernel<<<dim3(DIM / 128, BS / 128), 256, GSMEM>>>(
        p_mid, p_wh + WO_MLP2, b_mlp2, p_x2, out, BS, DIM, MLP_HID, 0, 5, 0,
        0, nullptr, nullptr);
}

// round 17
// speedup vs baseline: 1.0078x; 1.0078x over previous
#include <cuda_runtime.h>
#include <cuda_fp16.h>
#include <math.h>
#include <stdint.h>

#define DIM 1024
#define NH 16
#define HD 64
#define BATCH 4
#define SEQ 1024
#define BS (BATCH*SEQ)
#define MLP_HID 4096
#define LN_EPS 1e-5f

// ---------------- scratch ----------------
__device__ float  g_mod[BATCH * 6 * DIM];
__device__ __half g_h[BS * DIM];
__device__ __half g_qkv[BS * 3 * DIM];
__device__ __half g_o[BS * DIM];
__device__ float  g_x2[BS * DIM];
__device__ __half g_mid[BS * MLP_HID];
#define WO_QKV  0
#define WO_ATTN (3*DIM*DIM)
#define WO_MLP1 (WO_ATTN + DIM*DIM)
#define WO_MLP2 (WO_MLP1 + DIM*MLP_HID)
#define W_TOTAL (WO_MLP2 + MLP_HID*DIM)
__device__ __half g_wh[W_TOTAL];

// ================= helpers =================
__device__ __forceinline__ void mma16(float* c, const uint32_t* a, const uint32_t* b) {
    asm volatile(
        "mma.sync.aligned.m16n8k16.row.col.f32.f16.f16.f32 "
        "{%0,%1,%2,%3}, {%4,%5,%6,%7}, {%8,%9}, {%0,%1,%2,%3};"
        : "+f"(c[0]), "+f"(c[1]), "+f"(c[2]), "+f"(c[3])
        : "r"(a[0]), "r"(a[1]), "r"(a[2]), "r"(a[3]), "r"(b[0]), "r"(b[1]));
}
__device__ __forceinline__ void ldsm4(uint32_t* r, uint32_t addr) {
    asm volatile("ldmatrix.sync.aligned.m8n8.x4.shared.b16 {%0,%1,%2,%3}, [%4];"
        : "=r"(r[0]), "=r"(r[1]), "=r"(r[2]), "=r"(r[3]) : "r"(addr));
}
__device__ __forceinline__ void ldsm4t(uint32_t* r, uint32_t addr) {
    asm volatile("ldmatrix.sync.aligned.m8n8.x4.trans.shared.b16 {%0,%1,%2,%3}, [%4];"
        : "=r"(r[0]), "=r"(r[1]), "=r"(r[2]), "=r"(r[3]) : "r"(addr));
}
__device__ __forceinline__ void ldsm2t(uint32_t* r, uint32_t addr) {
    asm volatile("ldmatrix.sync.aligned.m8n8.x2.trans.shared.b16 {%0,%1}, [%2];"
        : "=r"(r[0]), "=r"(r[1]) : "r"(addr));
}
__device__ __forceinline__ uint32_t packh2(float a, float b) {
    __half2 h = __floats2half2_rn(a, b);
    return *(uint32_t*)&h;
}
__device__ __forceinline__ float gelu_f(float u) {
    float y = 0.7978845608028654f * (u + 0.044715f * u * u * u);
    float e = __expf(2.0f * y);
    return u * (1.0f - __fdividef(1.0f, e + 1.0f));
}

#define CP16(smem, gmem) \
    asm volatile("cp.async.cg.shared.global [%0], [%1], 16;" :: "r"(smem), "l"(gmem))
#define CP_COMMIT() asm volatile("cp.async.commit_group;" ::: "memory")
#define CP_WAIT1()  asm volatile("cp.async.wait_group 1;" ::: "memory")

// ---------------- prep1: qkv weight cvt + adaLN modulation ----------------
#define QKV_CVT_BLOCKS ((WO_ATTN/8 + 255)/256)
#define ADA_BLOCKS ((6*DIM + 255)/256)
__global__ void prep1_kernel(const float* __restrict__ wqkv,
                             const float* __restrict__ c,
                             const float* __restrict__ w_ada,
                             const float* __restrict__ b_ada)
{
    if (blockIdx.x < QKV_CVT_BLOCKS) {
        int i = (blockIdx.x * blockDim.x + threadIdx.x) * 8;
        if (i >= WO_ATTN) return;
        float4 v0 = *(const float4*)(wqkv + i);
        float4 v1 = *(const float4*)(wqkv + i + 4);
        uint4 u;
        u.x = packh2(v0.x, v0.y); u.y = packh2(v0.z, v0.w);
        u.z = packh2(v1.x, v1.y); u.w = packh2(v1.z, v1.w);
        *(uint4*)(g_wh + i) = u;
    } else {
        int j = (blockIdx.x - QKV_CVT_BLOCKS) * blockDim.x + threadIdx.x;
        if (j >= 6 * DIM) return;
        float s0 = b_ada[j], s1 = s0, s2 = s0, s3 = s0;
        for (int k = 0; k < DIM; k++) {
            float w = w_ada[k * (6 * DIM) + j];
            s0 += c[k] * w;
            s1 += c[DIM + k] * w;
            s2 += c[2 * DIM + k] * w;
            s3 += c[3 * DIM + k] * w;
        }
        g_mod[j] = s0;
        g_mod[6 * DIM + j] = s1;
        g_mod[12 * DIM + j] = s2;
        g_mod[18 * DIM + j] = s3;
    }
}

// ============ fp16 mma GEMM, BK=64, 2-stage cp.async, 2 CTA/SM ============
#define PADA 72
#define PADB 136
#define ASZH (128 * PADA)
#define BSZH (64 * PADB)
#define STGB ((ASZH + BSZH) * 2)
#define NSTAGE 2
#define GSMEM (NSTAGE * STGB)
#define EBROW 136

__global__ void __launch_bounds__(256, 2)
tgemm_kernel(const __half* __restrict__ A,
             const __half* __restrict__ B,
             const float* __restrict__ bias,
             const float* __restrict__ resid,
             void* __restrict__ C,
             int M, int N, int K, int act, int gate_chunk, int out_half,
             int rope, const float* __restrict__ cosb, const float* __restrict__ sinb)
{
    extern __shared__ char fsraw[];
    const uint32_t smb = (uint32_t)__cvta_generic_to_shared(fsraw);

    const int t = threadIdx.x, lane = t & 31, wid = t >> 5;
    const int warpM = wid >> 2, warpN = wid & 3;
    const int bm = blockIdx.y * 128, bn = blockIdx.x * 128;
    const int gid = lane >> 2, tig = lane & 3;

    const int am = (t * 8) >> 6;
    const int ak = (t * 8) & 63;
    const int bk = (t * 8) >> 7;
    const int bnn = (t * 8) & 127;

    float acc[4][4][4];
    #pragma unroll
    for (int i = 0; i < 4; i++)
        #pragma unroll
        for (int j = 0; j < 4; j++)
            #pragma unroll
            for (int q = 0; q < 4; q++) acc[i][j][q] = 0.f;

    const int NC = K >> 6;

    auto issue = [&](int stage, int kc) {
        uint32_t abase = smb + (uint32_t)(stage * STGB);
        uint32_t bbase = abase + (uint32_t)(ASZH * 2);
        #pragma unroll
        for (int i = 0; i < 4; i++) {
            int m = am + i * 32;
            CP16(abase + (uint32_t)(m * PADA + ak) * 2u,
                 A + (size_t)(bm + m) * K + kc * 64 + ak);
        }
        #pragma unroll
        for (int i = 0; i < 4; i++) {
            int kk = bk + i * 16;
            CP16(bbase + (uint32_t)(kk * PADB + bnn) * 2u,
                 B + (size_t)(kc * 64 + kk) * N + bn + bnn);
        }
    };

    issue(0, 0); CP_COMMIT();
    if (NC > 1) issue(1, 1);
    CP_COMMIT();

    const int arow = warpM * 64 + (lane & 15);
    const int akof = (lane >> 4) * 8;
    const int bkl = lane & 15;
    const int bgof = (lane >> 4) * 8;

    for (int kc = 0; kc < NC; kc++) {
        CP_WAIT1();
        __syncthreads();

        const uint32_t sA = smb + (uint32_t)((kc & 1) * STGB);
        const uint32_t sB = sA + (uint32_t)(ASZH * 2);

        #pragma unroll
        for (int ks = 0; ks < 4; ks++) {
            uint32_t af[4][4], bf[2][4];
            #pragma unroll
            for (int mi = 0; mi < 4; mi++) {
                int row = arow + mi * 16;
                ldsm4(af[mi], sA + (uint32_t)(row * PADA + ks * 16 + akof) * 2u);
            }
            #pragma unroll
            for (int g = 0; g < 2; g++) {
                int n0 = warpN * 32 + g * 16 + bgof;
                int k = ks * 16 + bkl;
                ldsm4t(bf[g], sB + (uint32_t)(k * PADB + n0) * 2u);
            }
            #pragma unroll
            for (int mi = 0; mi < 4; mi++)
                #pragma unroll
                for (int ni = 0; ni < 4; ni++)
                    mma16(acc[mi][ni], af[mi], &bf[ni >> 1][(ni & 1) * 2]);
        }

        if (kc + 2 < NC) {
            __syncthreads();
            issue(kc & 1, kc + 2);
        }
        CP_COMMIT();
    }

    // ---- epilogue ----
    if (rope && bn < 2 * DIM) {
        __half* eb = (__half*)fsraw;
        __syncthreads();
        #pragma unroll
        for (int mi = 0; mi < 4; mi++) {
            #pragma unroll
            for (int ni = 0; ni < 4; ni++) {
                int rl = warpM * 64 + mi * 16 + gid;
                int cl = warpN * 32 + ni * 8 + tig * 2;
                *(uint32_t*)&eb[rl * EBROW + cl] =
                    packh2(acc[mi][ni][0], acc[mi][ni][1]);
                *(uint32_t*)&eb[(rl + 8) * EBROW + cl] =
                    packh2(acc[mi][ni][2], acc[mi][ni][3]);
            }
        }
        __syncthreads();
        __half* Ch = (__half*)C;
        #pragma unroll
        for (int j = 0; j < 32; j++) {
            int p2 = j * 256 + t;
            int r = p2 >> 6;
            int q = p2 & 63;
            int hoff = (q >> 5) * 64;
            int i = q & 31;
            int grow = bm + r;
            int s = grow & (SEQ - 1);
            float co = cosb[s * 32 + i];
            float si = sinb[s * 32 + i];
            float v1 = __half2float(eb[r * EBROW + hoff + i]);
            float v2 = __half2float(eb[r * EBROW + hoff + i + 32]);
            size_t base = (size_t)grow * N + bn + hoff;
            Ch[base + i]      = __float2half_rn(v1 * co - v2 * si);
            Ch[base + i + 32] = __float2half_rn(v2 * co + v1 * si);
        }
        return;
    }

    #pragma unroll
    for (int mi = 0; mi < 4; mi++) {
        #pragma unroll
        for (int ni = 0; ni < 4; ni++) {
            int r0 = bm + warpM * 64 + mi * 16 + gid;
            int c0 = bn + warpN * 32 + ni * 8 + tig * 2;
            float v0 = acc[mi][ni][0], v1 = acc[mi][ni][1];
            float v2 = acc[mi][ni][2], v3 = acc[mi][ni][3];
            if (bias) {
                float b0 = bias[c0], b1 = bias[c0 + 1];
                v0 += b0; v1 += b1; v2 += b0; v3 += b1;
            }
            if (act) {
                v0 = gelu_f(v0); v1 = gelu_f(v1);
                v2 = gelu_f(v2); v3 = gelu_f(v3);
            }
            if (resid) {
                const float* gp0 = g_mod + (r0 >> 10) * 6 * DIM + gate_chunk * DIM + c0;
                const float* gp1 = g_mod + ((r0 + 8) >> 10) * 6 * DIM + gate_chunk * DIM + c0;
                float2 rr0 = *(const float2*)(resid + (size_t)r0 * N + c0);
                float2 rr1 = *(const float2*)(resid + (size_t)(r0 + 8) * N + c0);
                v0 = rr0.x + gp0[0] * v0;
                v1 = rr0.y + gp0[1] * v1;
                v2 = rr1.x + gp1[0] * v2;
                v3 = rr1.y + gp1[1] * v3;
            }
            if (out_half) {
                __half* Ch = (__half*)C;
                *(uint32_t*)(Ch + (size_t)r0 * N + c0)       = packh2(v0, v1);
                *(uint32_t*)(Ch + (size_t)(r0 + 8) * N + c0) = packh2(v2, v3);
            } else {
                float* Cf = (float*)C;
                *(float2*)(Cf + (size_t)r0 * N + c0)       = make_float2(v0, v1);
                *(float2*)(Cf + (size_t)(r0 + 8) * N + c0) = make_float2(v2, v3);
            }
        }
    }
}

// ============ fused flash attention (2-buffer K/V ring, 4 CTA/SM) + cvt ============
#define FP 72
#define KVT (64 * FP)
#define FLASH_BLOCKS 1024
#define REST_ELEMS (W_TOTAL - WO_ATTN)
#define CVT2_PER (128 * 8 * 4)
#define CVT2_BLOCKS ((REST_ELEMS + CVT2_PER - 1) / CVT2_PER)

__global__ void __launch_bounds__(128)
flash_kernel(const float* __restrict__ wattn,
             const float* __restrict__ wmlp1,
             const float* __restrict__ wmlp2)
{
    __shared__ __align__(16) __half Qs[KVT];
    __shared__ __align__(16) __half Ks[2][KVT];
    __shared__ __align__(16) __half Vs[2][KVT];

    const int bid = blockIdx.x;
    const int t = threadIdx.x;

    if (bid >= FLASH_BLOCKS) {
        int base = (bid - FLASH_BLOCKS) * CVT2_PER + t * 8;
        #pragma unroll
        for (int it2 = 0; it2 < 4; it2++) {
            int i = base + it2 * 1024;
            if (i >= REST_ELEMS) return;
            const float* src;
            int off;
            if (i < WO_MLP1 - WO_ATTN)      { src = wattn; off = i; }
            else if (i < WO_MLP2 - WO_ATTN) { src = wmlp1; off = i - (WO_MLP1 - WO_ATTN); }
            else                            { src = wmlp2; off = i - (WO_MLP2 - WO_ATTN); }
            float4 v0 = *(const float4*)(src + off);
            float4 v1 = *(const float4*)(src + off + 4);
            uint4 u;
            u.x = packh2(v0.x, v0.y); u.y = packh2(v0.z, v0.w);
            u.z = packh2(v1.x, v1.y); u.w = packh2(v1.z, v1.w);
            *(uint4*)(g_wh + WO_ATTN + i) = u;
        }
        return;
    }

    const int lane = t & 31, wid = t >> 5;
    const int gid = lane >> 2, tig = lane & 3;
    const int bh = bid >> 4, b = bh >> 4, h = bh & 15;
    const int q0 = (bid & 15) * 64;
    const int row = wid * 16 + gid;

    const int fr = (t * 8) >> 6;
    const int fc = (t * 8) & 63;

    auto issue_kv = [&](int buf, int kt) {
        uint32_t kb = (uint32_t)__cvta_generic_to_shared(&Ks[buf][0]);
        uint32_t vbuf = (uint32_t)__cvta_generic_to_shared(&Vs[buf][0]);
        #pragma unroll
        for (int i = 0; i < 4; i++) {
            int r = fr + i * 16;
            const __half* kg = g_qkv + ((size_t)(b * SEQ + kt + r) * 3 + 1) * 1024 + h * 64 + fc;
            const __half* vg = g_qkv + ((size_t)(b * SEQ + kt + r) * 3 + 2) * 1024 + h * 64 + fc;
            CP16(kb   + (uint32_t)(r * FP + fc) * 2u, kg);
            CP16(vbuf + (uint32_t)(r * FP + fc) * 2u, vg);
        }
    };

    #pragma unroll
    for (int i = 0; i < 4; i++) {
        int e = (i * 128 + t) * 8;
        int r = e >> 6, c = e & 63;
        *(uint4*)&Qs[r * FP + c] =
            *(const uint4*)(g_qkv + ((size_t)(b * SEQ + q0 + r) * 3) * 1024 + h * 64 + c);
    }

    issue_kv(0, 0); CP_COMMIT();
    issue_kv(1, 64); CP_COMMIT();

    float m_i[2] = { -1e30f, -1e30f };
    float l_i[2] = { 0.f, 0.f };
    float oacc[8][4];
    #pragma unroll
    for (int ni = 0; ni < 8; ni++)
        #pragma unroll
        for (int q = 0; q < 4; q++) oacc[ni][q] = 0.f;

    for (int it = 0; it < SEQ / 64; it++) {
        CP_WAIT1();
        __syncthreads();           // tile `it` visible

        const __half* Kc = Ks[it & 1];
        const uint32_t vb = (uint32_t)__cvta_generic_to_shared(&Vs[it & 1][0]);

        float sacc[8][4];
        #pragma unroll
        for (int ni = 0; ni < 8; ni++)
            #pragma unroll
            for (int q = 0; q < 4; q++) sacc[ni][q] = 0.f;

        #pragma unroll
        for (int ks = 0; ks < 4; ks++) {
            uint32_t af[4];
            af[0] = *(uint32_t*)&Qs[row * FP + ks * 16 + 2 * tig];
            af[1] = *(uint32_t*)&Qs[(row + 8) * FP + ks * 16 + 2 * tig];
            af[2] = *(uint32_t*)&Qs[row * FP + ks * 16 + 8 + 2 * tig];
            af[3] = *(uint32_t*)&Qs[(row + 8) * FP + ks * 16 + 8 + 2 * tig];
            #pragma unroll
            for (int ni = 0; ni < 8; ni++) {
                int n = ni * 8 + gid;
                uint32_t bf[2];
                bf[0] = *(const uint32_t*)&Kc[n * FP + ks * 16 + 2 * tig];
                bf[1] = *(const uint32_t*)&Kc[n * FP + ks * 16 + 8 + 2 * tig];
                mma16(sacc[ni], af, bf);
            }
        }

        #pragma unroll
        for (int ni = 0; ni < 8; ni++)
            #pragma unroll
            for (int q = 0; q < 4; q++) sacc[ni][q] *= 0.125f;

        float rmax[2] = { -1e30f, -1e30f };
        #pragma unroll
        for (int ni = 0; ni < 8; ni++) {
            rmax[0] = fmaxf(rmax[0], fmaxf(sacc[ni][0], sacc[ni][1]));
            rmax[1] = fmaxf(rmax[1], fmaxf(sacc[ni][2], sacc[ni][3]));
        }
        #pragma unroll
        for (int w = 1; w <= 2; w <<= 1) {
            rmax[0] = fmaxf(rmax[0], __shfl_xor_sync(0xffffffff, rmax[0], w));
            rmax[1] = fmaxf(rmax[1], __shfl_xor_sync(0xffffffff, rmax[1], w));
        }
        float mnew0 = fmaxf(m_i[0], rmax[0]);
        float mnew1 = fmaxf(m_i[1], rmax[1]);
        float alpha0 = __expf(m_i[0] - mnew0);
        float alpha1 = __expf(m_i[1] - mnew1);
        m_i[0] = mnew0; m_i[1] = mnew1;

        float rsum[2] = { 0.f, 0.f };
        #pragma unroll
        for (int ni = 0; ni < 8; ni++) {
            sacc[ni][0] = __expf(sacc[ni][0] - mnew0);
            sacc[ni][1] = __expf(sacc[ni][1] - mnew0);
            sacc[ni][2] = __expf(sacc[ni][2] - mnew1);
            sacc[ni][3] = __expf(sacc[ni][3] - mnew1);
            rsum[0] += sacc[ni][0] + sacc[ni][1];
            rsum[1] += sacc[ni][2] + sacc[ni][3];
        }
        #pragma unroll
        for (int w = 1; w <= 2; w <<= 1) {
            rsum[0] += __shfl_xor_sync(0xffffffff, rsum[0], w);
            rsum[1] += __shfl_xor_sync(0xffffffff, rsum[1], w);
        }
        l_i[0] = l_i[0] * alpha0 + rsum[0];
        l_i[1] = l_i[1] * alpha1 + rsum[1];

        #pragma unroll
        for (int ni = 0; ni < 8; ni++) {
            oacc[ni][0] *= alpha0; oacc[ni][1] *= alpha0;
            oacc[ni][2] *= alpha1; oacc[ni][3] *= alpha1;
        }

        #pragma unroll
        for (int ks = 0; ks < 4; ks++) {
            uint32_t af[4];
            af[0] = packh2(sacc[2*ks][0],   sacc[2*ks][1]);
            af[1] = packh2(sacc[2*ks][2],   sacc[2*ks][3]);
            af[2] = packh2(sacc[2*ks+1][0], sacc[2*ks+1][1]);
            af[3] = packh2(sacc[2*ks+1][2], sacc[2*ks+1][3]);
            int k = ks * 16 + (lane & 15);
            #pragma unroll
            for (int ni = 0; ni < 8; ni++) {
                uint32_t bf[2];
                ldsm2t(bf, vb + (uint32_t)(k * FP + ni * 8) * 2u);
                mma16(oacc[ni], af, bf);
            }
        }

        // re-issue into the buffer just consumed (needs all warps done)
        if (it + 2 < SEQ / 64) {
            __syncthreads();
            issue_kv(it & 1, (it + 2) * 64);
        }
        CP_COMMIT();
    }

    float inv0 = __fdividef(1.0f, l_i[0]);
    float inv1 = __fdividef(1.0f, l_i[1]);
    #pragma unroll
    for (int ni = 0; ni < 8; ni++) {
        int c = h * 64 + ni * 8 + tig * 2;
        __half* op0 = g_o + (size_t)(b * SEQ + q0 + row) * 1024 + c;
        __half* op1 = g_o + (size_t)(b * SEQ + q0 + row + 8) * 1024 + c;
        *(uint32_t*)op0 = packh2(oacc[ni][0] * inv0, oacc[ni][1] * inv0);
        *(uint32_t*)op1 = packh2(oacc[ni][2] * inv1, oacc[ni][3] * inv1);
    }
}

// ---------------- LayerNorm + modulate -> half (shuffle reduction) ----------------
__global__ void ln_mod_kernel(const float* __restrict__ x,
                              const float* __restrict__ w,
                              int shift_chunk, int scale_chunk,
                              __half* __restrict__ out)
{
    int row = blockIdx.x;
    int b = row >> 10;
    int t = threadIdx.x;
    int lane = t & 31, wid = t >> 5;
    const float* xr = x + (size_t)row * DIM;
    float4 v = *(const float4*)(xr + t * 4);
    float sum = v.x + v.y + v.z + v.w;
    float sq  = v.x*v.x + v.y*v.y + v.z*v.z + v.w*v.w;

    #pragma unroll
    for (int o = 16; o > 0; o >>= 1) {
        sum += __shfl_xor_sync(0xffffffff, sum, o);
        sq  += __shfl_xor_sync(0xffffffff, sq,  o);
    }
    __shared__ float ws[8], ws2[8];
    if (lane == 0) { ws[wid] = sum; ws2[wid] = sq; }
    __syncthreads();
    if (wid == 0) {
        float a = (lane < 8) ? ws[lane] : 0.f;
        float c2 = (lane < 8) ? ws2[lane] : 0.f;
        #pragma unroll
        for (int o = 4; o > 0; o >>= 1) {
            a  += __shfl_xor_sync(0xffffffff, a, o);
            c2 += __shfl_xor_sync(0xffffffff, c2, o);
        }
        if (lane == 0) { ws[0] = a; ws2[0] = c2; }
    }
    __syncthreads();
    float mean = ws[0] * (1.0f / DIM);
    float var  = ws2[0] * (1.0f / DIM) - mean * mean;
    float rstd = rsqrtf(var + LN_EPS);

    const float* shiftp = g_mod + b * 6 * DIM + shift_chunk * DIM;
    const float* scalep = g_mod + b * 6 * DIM + scale_chunk * DIM;
    __half* orow = out + (size_t)row * DIM;
    float y[4];
    #pragma unroll
    for (int u = 0; u < 4; u++) {
        int col = t * 4 + u;
        float xv = (u == 0) ? v.x : (u == 1) ? v.y : (u == 2) ? v.z : v.w;
        float yy = (xv - mean) * rstd * w[col];
        y[u] = yy * (1.0f + scalep[col]) + shiftp[col];
    }
    uint2 pk;
    pk.x = packh2(y[0], y[1]);
    pk.y = packh2(y[2], y[3]);
    *(uint2*)(orow + t * 4) = pk;
}

// ---------------- launch ----------------
extern "C" void kernel_launch(void* const* d_in, const int* in_sizes, int n_in,
                              void* d_out, int out_size)
{
    const float* x          = (const float*)d_in[0];
    const float* cosb       = (const float*)d_in[1];
    const float* sinb       = (const float*)d_in[2];
    const float* c          = (const float*)d_in[3];
    const float* w_ln1      = (const float*)d_in[4];
    const float* w_ln2      = (const float*)d_in[5];
    const float* w_qkv      = (const float*)d_in[6];
    const float* w_attn_out = (const float*)d_in[7];
    const float* w_mlp1     = (const float*)d_in[8];
    const float* b_mlp1     = (const float*)d_in[9];
    const float* w_mlp2     = (const float*)d_in[10];
    const float* b_mlp2     = (const float*)d_in[11];
    const float* w_ada      = (const float*)d_in[12];
    const float* b_ada      = (const float*)d_in[13];
    float* out = (float*)d_out;

    __half *p_h, *p_qkv, *p_o, *p_mid, *p_wh;
    float *p_x2;
    cudaGetSymbolAddress((void**)&p_h,   g_h);
    cudaGetSymbolAddress((void**)&p_qkv, g_qkv);
    cudaGetSymbolAddress((void**)&p_o,   g_o);
    cudaGetSymbolAddress((void**)&p_x2,  g_x2);
    cudaGetSymbolAddress((void**)&p_mid, g_mid);
    cudaGetSymbolAddress((void**)&p_wh,  g_wh);

    cudaFuncSetAttribute(tgemm_kernel,
                         cudaFuncAttributeMaxDynamicSharedMemorySize, GSMEM);

    // 1. qkv weight cvt + adaLN modulation
    prep1_kernel<<<QKV_CVT_BLOCKS + ADA_BLOCKS, 256>>>(w_qkv, c, w_ada, b_ada);

    // 2. LN1 + modulate
    ln_mod_kernel<<<BS, 256>>>(x, w_ln1, 0, 1, p_h);

    // 3. qkv = h @ w_qkv  (RoPE fused into epilogue for q/k planes)
    tgemm_kernel<<<dim3(3 * DIM / 128, BS / 128), 256, GSMEM>>>(
        p_h, p_wh + WO_QKV, nullptr, nullptr, p_qkv, BS, 3 * DIM, DIM, 0, 0, 1,
        1, cosb, sinb);

    // 4. fused attention + hidden attn/mlp weight conversion
    flash_kernel<<<FLASH_BLOCKS + CVT2_BLOCKS, 128>>>(w_attn_out, w_mlp1, w_mlp2);

    // 5. x2 = x + gate_msa * (o @ w_attn_out)
    tgemm_kernel<<<dim3(DIM / 128, BS / 128), 256, GSMEM>>>(
        p_o, p_wh + WO_ATTN, nullptr, x, p_x2, BS, DIM, DIM, 0, 2, 0,
        0, nullptr, nullptr);

    // 6. LN2 + modulate
    ln_mod_kernel<<<BS, 256>>>(p_x2, w_ln2, 3, 4, p_h);

    // 7. mid = gelu(h @ w_mlp1 + b_mlp1)
    tgemm_kernel<<<dim3(MLP_HID / 128, BS / 128), 256, GSMEM>>>(
        p_h, p_wh + WO_MLP1, b_mlp1, nullptr, p_mid, BS, MLP_HID, DIM, 1, 0, 1,
        0, nullptr, nullptr);

    // 8. out = x2 + gate_mlp * (mid @ w_mlp2 + b_mlp2)
    tgemm_kernel<<<dim3(DIM / 128, BS / 128), 256, GSMEM>>>(
        p_mid, p_wh + WO_MLP2, b_mlp2, p_x2, out, BS, DIM, MLP_HID, 0, 5, 0,
        0, nullptr, nullptr);
}